// round 3
// baseline (speedup 1.0000x reference)
#include <cuda_runtime.h>
#include <cuda_fp16.h>

// LNCC fully fused: z-filter (in-thread) + y-filter (smem exchange) +
// x-filter (per-thread ring, running sums) + NCC + global reduction,
// all in ONE kernel launch. Volumes (2,1,192,192,192) fp32, kernel 5,
// zero padding; normalizer always 1/125.

#define NN     192
#define V      14155776          // 2*192^3
#define TPB    128
#define YT     32                // y rows per block
#define Z4T    4                 // z float4-groups per block (16 z)
#define XCHUNK 48
#define NXC    4                 // 192/48
#define NYT    6                 // 192/32
#define NZT    12                // 192/16
#define NBLK   (2 * NYT * NZT * NXC)   // 576
#define ZROWS  (YT + 4)          // 36 rows incl. y halo
#define ZPAD   21                // uint2 per zbuf row (20 used + 1 pad)

__device__ double   g_acc;       // zero at load; self-resetting per launch
__device__ unsigned g_cnt;

// 5-tap sliding window sums over p0..p7 -> 4 outputs (fp32).
__device__ __forceinline__ float4 win5(float p0, float p1, float p2, float p3,
                                       float p4, float p5, float p6, float p7) {
    float s0 = ((p0 + p1) + (p2 + p3)) + p4;
    float s1 = s0 - p0 + p5;
    float s2 = s1 - p1 + p6;
    float s3 = s2 - p2 + p7;
    return make_float4(s0, s1, s2, s3);
}

__device__ __forceinline__ uint2 packh4(float4 s) {
    union { uint2 u; __half2 h[2]; } pk;
    pk.h[0] = __floats2half2_rn(s.x, s.y);
    pk.h[1] = __floats2half2_rn(s.z, s.w);
    return pk.u;
}

__device__ __forceinline__ float4 unpackh4(uint2 u) {
    union { uint2 u; __half2 h[2]; } pk;
    pk.u = u;
    float2 a = __half22float2(pk.h[0]);
    float2 b = __half22float2(pk.h[1]);
    return make_float4(a.x, a.y, b.x, b.y);
}

__global__ void __launch_bounds__(TPB, 4)
k_fused(const float* __restrict__ I, const float* __restrict__ J,
        float* __restrict__ out) {
    __shared__ uint2 zbuf[2][ZROWS][ZPAD];   // z-filtered fp16 slices (dbl-buf)
    __shared__ uint2 ring[5][5][TPB];        // x-window ring [slot][ch][tid]
    __shared__ float ws[TPB / 32];

    int tid = threadIdx.x;
    int bid = blockIdx.x;
    int xc = bid & (NXC - 1);
    int r  = bid >> 2;
    int zt = r % NZT; r /= NZT;
    int yt = r % NYT;
    int b  = r / NYT;

    int z4l = tid & 3;            // local z group 0..3
    int yl  = tid >> 2;           // local y row 0..31
    int x0  = xc * XCHUNK;
    int ybase = yt * YT;
    int zg0   = zt * Z4T;

    float acc[5][4];
#pragma unroll
    for (int c = 0; c < 5; c++)
#pragma unroll
        for (int j = 0; j < 4; j++) acc[c][j] = 0.f;

    float local = 0.f;
    const float inv = 1.0f / 125.0f;
    const float4 zero4 = make_float4(0.f, 0.f, 0.f, 0.f);

    int slot = 4;                               // becomes 0 at t=0

    for (int t = 0; t < XCHUNK + 4; t++) {
        int x = x0 - 2 + t;
        int pbuf = t & 1;

        // ---- Phase A: z-filter the (x, y-halo rows, z-tile) slice -> zbuf
        if ((unsigned)x < (unsigned)NN) {
#pragma unroll 1
            for (int task = tid; task < ZROWS * Z4T; task += TPB) {
                int tz = task & 3;
                int ty = task >> 2;
                int yy = ybase - 2 + ty;
                float4 s[5];
                if ((unsigned)yy < (unsigned)NN) {
                    int zg = zg0 + tz;
                    int base = ((b * NN + x) * NN + yy) * NN + zg * 4;
                    const float4* pi = reinterpret_cast<const float4*>(I + base);
                    const float4* pj = reinterpret_cast<const float4*>(J + base);
                    float4 im = (zg > 0)  ? pi[-1] : zero4;
                    float4 ib = pi[0];
                    float4 ip = (zg < 47) ? pi[1]  : zero4;
                    float4 jm = (zg > 0)  ? pj[-1] : zero4;
                    float4 jb = pj[0];
                    float4 jp = (zg < 47) ? pj[1]  : zero4;
                    float i0 = im.z, i1 = im.w, i2 = ib.x, i3 = ib.y,
                          i4 = ib.z, i5 = ib.w, i6 = ip.x, i7 = ip.y;
                    float j0 = jm.z, j1 = jm.w, j2 = jb.x, j3 = jb.y,
                          j4 = jb.z, j5 = jb.w, j6 = jp.x, j7 = jp.y;
                    s[0] = win5(i0, i1, i2, i3, i4, i5, i6, i7);
                    s[1] = win5(j0, j1, j2, j3, j4, j5, j6, j7);
                    s[2] = win5(i0*i0, i1*i1, i2*i2, i3*i3, i4*i4, i5*i5, i6*i6, i7*i7);
                    s[3] = win5(j0*j0, j1*j1, j2*j2, j3*j3, j4*j4, j5*j5, j6*j6, j7*j7);
                    s[4] = win5(i0*j0, i1*j1, i2*j2, i3*j3, i4*j4, i5*j5, i6*j6, i7*j7);
                } else {
#pragma unroll
                    for (int c = 0; c < 5; c++) s[c] = zero4;
                }
#pragma unroll
                for (int c = 0; c < 5; c++)
                    zbuf[pbuf][ty][c * 4 + tz] = packh4(s[c]);
            }
        } else {
#pragma unroll 1
            for (int task = tid; task < ZROWS * Z4T; task += TPB) {
                int tz = task & 3;
                int ty = task >> 2;
#pragma unroll
                for (int c = 0; c < 5; c++)
                    zbuf[pbuf][ty][c * 4 + tz] = make_uint2(0u, 0u);
            }
        }
        __syncthreads();

        // ---- Phase B: y-filter (5-tap half2 sums from zbuf)
        __half2 zlo[5], zhi[5];
#pragma unroll
        for (int c = 0; c < 5; c++) {
            uint2 u = zbuf[pbuf][yl][c * 4 + z4l];
            __half2 a0 = *reinterpret_cast<__half2*>(&u.x);
            __half2 a1 = *reinterpret_cast<__half2*>(&u.y);
#pragma unroll
            for (int dy = 1; dy < 5; dy++) {
                uint2 v = zbuf[pbuf][yl + dy][c * 4 + z4l];
                a0 = __hadd2(a0, *reinterpret_cast<__half2*>(&v.x));
                a1 = __hadd2(a1, *reinterpret_cast<__half2*>(&v.y));
            }
            zlo[c] = a0; zhi[c] = a1;
        }

        // ---- Phase C: x ring update (exact fp16 cancel: store what we add)
        slot = (slot == 4) ? 0 : slot + 1;
        if (t >= 5) {
#pragma unroll
            for (int c = 0; c < 5; c++) {
                float4 o = unpackh4(ring[slot][c][tid]);
                acc[c][0] -= o.x; acc[c][1] -= o.y;
                acc[c][2] -= o.z; acc[c][3] -= o.w;
            }
        }
#pragma unroll
        for (int c = 0; c < 5; c++) {
            union { uint2 u; __half2 h[2]; } pk;
            pk.h[0] = zlo[c]; pk.h[1] = zhi[c];
            ring[slot][c][tid] = pk.u;
            float2 f0 = __half22float2(zlo[c]);
            float2 f1 = __half22float2(zhi[c]);
            acc[c][0] += f0.x; acc[c][1] += f0.y;
            acc[c][2] += f1.x; acc[c][3] += f1.y;
        }

        // ---- Phase D: NCC for output column x_out = x-2 (valid when t>=4)
        if (t >= 4) {
#pragma unroll
            for (int j = 0; j < 4; j++) {
                float uI  = acc[0][j] * inv;
                float uJ  = acc[1][j] * inv;
                float mI2 = acc[2][j] * inv;
                float mJ2 = acc[3][j] * inv;
                float mIJ = acc[4][j] * inv;
                float cross = mIJ - uI * uJ;
                float vI = mI2 - uI * uI;
                float vJ = mJ2 - uJ * uJ;
                local += __fdividef(cross * cross, vI * vJ + 1e-5f);
            }
        }
        __syncthreads();   // protect zbuf[pbuf] (reused at t+2) vs Phase A writes
    }

    // ---- block reduction -> global double atomic -> last-block finalize
#pragma unroll
    for (int o = 16; o; o >>= 1)
        local += __shfl_down_sync(0xffffffffu, local, o);
    int lane = tid & 31, wid = tid >> 5;
    if (lane == 0) ws[wid] = local;
    __syncthreads();
    if (tid == 0) {
        float v = ws[0] + ws[1] + ws[2] + ws[3];
        atomicAdd(&g_acc, (double)v);
        __threadfence();
        unsigned done = atomicAdd(&g_cnt, 1u);
        if (done == (unsigned)(NBLK - 1)) {
            double total = atomicAdd(&g_acc, 0.0);   // L2-coherent read
            out[0] = (float)(-total / (double)V);
            g_acc = 0.0;                              // reset for next replay
            g_cnt = 0u;
            __threadfence();
        }
    }
}

extern "C" void kernel_launch(void* const* d_in, const int* in_sizes, int n_in,
                              void* d_out, int out_size) {
    const float* pred = (const float*)d_in[0];
    const float* targ = (const float*)d_in[1];
    (void)in_sizes; (void)n_in; (void)out_size;
    k_fused<<<NBLK, TPB>>>(pred, targ, (float*)d_out);
}